// round 3
// baseline (speedup 1.0000x reference)
#include <cuda_runtime.h>

// ----------------------------------------------------------------------------
// RNNDecoder: 3-layer GRU (H=128), T=256 steps, B=1024, fc head (out_dim=2).
//
// Design:
//   - Batch rows are independent across the whole recurrence -> each CTA owns
//     BC=8 rows and runs all 256*3 cells locally (no inter-CTA sync).
//   - grid = 128 CTAs x 384 threads. Thread j computes gate-row j of both
//     GEMVs (gx = W_ih x, gh = W_hh h) for its 8 batch rows.
//   - Weights pre-transposed once per launch (prep kernel) into
//     [l][kchunk][j] float4 layout -> warp weight loads are 512B coalesced.
//   - Activations in smem as [k][b] (b contiguous) -> packed-pair FMA via
//     fma.rn.f32x2 (2x fp32 FMA throughput vs plain FFMA on sm_103a).
//   - Gate combine + GRU update + fc head all in-CTA; 2 barriers per cell.
// ----------------------------------------------------------------------------

namespace {
constexpr int LAYERS = 3;
constexpr int H      = 128;
constexpr int G3     = 3 * H;        // 384 gate rows
constexpr int T      = 256;
constexpr int BATCH  = 1024;
constexpr int BC     = 8;            // batch rows per CTA
constexpr int NTHR   = G3;           // 384 threads
constexpr int NBLK   = BATCH / BC;   // 128 CTAs
constexpr int KK     = H / 4;        // 32 float4 chunks along K
}

// Transposed weights (scratch; __device__ globals, no allocation).
__device__ float4 g_wt_ih[LAYERS * KK * G3];
__device__ float4 g_wt_hh[LAYERS * KK * G3];

__global__ void prep_kernel(const float* __restrict__ wih,
                            const float* __restrict__ whh) {
  int idx = blockIdx.x * blockDim.x + threadIdx.x;
  if (idx >= LAYERS * KK * G3) return;
  int j  = idx % G3;
  int r  = idx / G3;
  int kk = r % KK;
  int l  = r / KK;
  g_wt_ih[idx] = *reinterpret_cast<const float4*>(wih + (l * G3 + j) * H + kk * 4);
  g_wt_hh[idx] = *reinterpret_cast<const float4*>(whh + (l * G3 + j) * H + kk * 4);
}

__device__ __forceinline__ void ffma2(unsigned long long& a,
                                      unsigned long long w,
                                      unsigned long long x) {
  asm("fma.rn.f32x2 %0, %1, %2, %0;" : "+l"(a) : "l"(w), "l"(x));
}
__device__ __forceinline__ unsigned long long dup2(float w) {
  unsigned long long r;
  asm("mov.b64 %0, {%1, %1};" : "=l"(r) : "f"(w));
  return r;
}
__device__ __forceinline__ float2 unpk(unsigned long long v) {
  float lo, hi;
  asm("mov.b64 {%0, %1}, %2;" : "=f"(lo), "=f"(hi) : "l"(v));
  return make_float2(lo, hi);
}
__device__ __forceinline__ float sigm(float x) {
  return __fdividef(1.0f, 1.0f + __expf(-x));
}
__device__ __forceinline__ float tanh_fast(float v) {
  float a = fabsf(v);
  float e = __expf(-2.0f * a);
  float r = __fdividef(1.0f - e, 1.0f + e);
  return copysignf(r, v);
}

__global__ void __launch_bounds__(NTHR, 1)
gru_kernel(const float* __restrict__ hiddens,
           const float* __restrict__ b_ih,
           const float* __restrict__ b_hh,
           const float* __restrict__ fc_w,
           const float* __restrict__ fc_b,
           float* __restrict__ out) {
  // Activations: [k][b], b contiguous -> packed-pair (f32x2) friendly.
  __shared__ __align__(16) float s_x[H * BC];            // input to current layer
  __shared__ __align__(16) float s_h[LAYERS * H * BC];   // hidden state per layer
  __shared__ __align__(16) float s_sum[2 * H * BC];      // r,z pre-activations (gx+gh+b)
  __shared__ __align__(16) float s_gxn[H * BC];          // n-gate x part (+b_ih)
  __shared__ __align__(16) float s_ghn[H * BC];          // n-gate h part (+b_hh)
  __shared__ float s_fcw[2 * H];
  __shared__ float s_fcb[2];

  const int tid = threadIdx.x;
  const int j   = tid;                  // gate row owned by this thread
  const int b0  = blockIdx.x * BC;

  // Per-thread biases (fixed j across all cells; layer varies).
  float bA[LAYERS], bB[LAYERS];
#pragma unroll
  for (int l = 0; l < LAYERS; l++) {
    if (j < 2 * H) {            // r,z gates use b_ih + b_hh summed
      bA[l] = b_ih[l * G3 + j] + b_hh[l * G3 + j];
      bB[l] = 0.0f;
    } else {                    // n gate keeps them separate (r multiplies gh+bh)
      bA[l] = b_ih[l * G3 + j];
      bB[l] = b_hh[l * G3 + j];
    }
  }
  if (tid < 2 * H) s_fcw[tid] = fc_w[tid];
  if (tid < 2)     s_fcb[tid] = fc_b[tid];

  // h init: hiddens[b][l][k] -> s_h[l][k][b]
  for (int idx = tid; idx < LAYERS * H * BC; idx += NTHR) {
    int l   = idx / (H * BC);
    int rem = idx - l * (H * BC);
    int k   = rem >> 3;
    int b   = rem & 7;
    s_h[idx] = hiddens[(b0 + b) * (LAYERS * H) + l * H + k];
  }
  for (int idx = tid; idx < H * BC; idx += NTHR) s_x[idx] = 0.0f;  // x0 = zeros
  __syncthreads();

  for (int t = 0; t < T; t++) {
#pragma unroll 1
    for (int l = 0; l < LAYERS; l++) {
      const float4* __restrict__ wxp = g_wt_ih + l * (KK * G3) + j;
      const float4* __restrict__ whp = g_wt_hh + l * (KK * G3) + j;
      const float*  __restrict__ hl  = s_h + l * (H * BC);

      unsigned long long ax0 = 0, ax1 = 0, ax2 = 0, ax3 = 0;
      unsigned long long ah0 = 0, ah1 = 0, ah2 = 0, ah3 = 0;

#define STEPK(WXE, WHE, KIDX)                                              \
      {                                                                    \
        unsigned long long w2x = dup2(WXE), w2h = dup2(WHE);               \
        ulonglong2 xv0 = *reinterpret_cast<const ulonglong2*>(s_x + (KIDX) * 8);     \
        ulonglong2 xv1 = *reinterpret_cast<const ulonglong2*>(s_x + (KIDX) * 8 + 4); \
        ulonglong2 hv0 = *reinterpret_cast<const ulonglong2*>(hl  + (KIDX) * 8);     \
        ulonglong2 hv1 = *reinterpret_cast<const ulonglong2*>(hl  + (KIDX) * 8 + 4); \
        ffma2(ax0, w2x, xv0.x); ffma2(ax1, w2x, xv0.y);                    \
        ffma2(ax2, w2x, xv1.x); ffma2(ax3, w2x, xv1.y);                    \
        ffma2(ah0, w2h, hv0.x); ffma2(ah1, w2h, hv0.y);                    \
        ffma2(ah2, w2h, hv1.x); ffma2(ah3, w2h, hv1.y);                    \
      }

#pragma unroll 4
      for (int kk = 0; kk < KK; kk++) {
        float4 w4x = wxp[kk * G3];
        float4 w4h = whp[kk * G3];
        int kb = kk * 4;
        STEPK(w4x.x, w4h.x, kb + 0)
        STEPK(w4x.y, w4h.y, kb + 1)
        STEPK(w4x.z, w4h.z, kb + 2)
        STEPK(w4x.w, w4h.w, kb + 3)
      }
#undef STEPK

      float2 x0 = unpk(ax0), x1 = unpk(ax1), x2 = unpk(ax2), x3 = unpk(ax3);
      float2 h0 = unpk(ah0), h1 = unpk(ah1), h2 = unpk(ah2), h3 = unpk(ah3);

      if (j < 2 * H) {
        float bs = bA[l];
        float4* d = reinterpret_cast<float4*>(s_sum + j * 8);
        d[0] = make_float4(x0.x + h0.x + bs, x0.y + h0.y + bs,
                           x1.x + h1.x + bs, x1.y + h1.y + bs);
        d[1] = make_float4(x2.x + h2.x + bs, x2.y + h2.y + bs,
                           x3.x + h3.x + bs, x3.y + h3.y + bs);
      } else {
        int jn = j - 2 * H;
        float bx = bA[l], bh = bB[l];
        float4* dx = reinterpret_cast<float4*>(s_gxn + jn * 8);
        float4* dh = reinterpret_cast<float4*>(s_ghn + jn * 8);
        dx[0] = make_float4(x0.x + bx, x0.y + bx, x1.x + bx, x1.y + bx);
        dx[1] = make_float4(x2.x + bx, x2.y + bx, x3.x + bx, x3.y + bx);
        dh[0] = make_float4(h0.x + bh, h0.y + bh, h1.x + bh, h1.y + bh);
        dh[1] = make_float4(h2.x + bh, h2.y + bh, h3.x + bh, h3.y + bh);
      }
      __syncthreads();

      // Gate combine + state update. tid -> (b = tid&7, j0 = tid>>3),
      // offsets tid + 256q are lane-consecutive -> conflict-free smem.
      if (tid < 2 * H) {
#pragma unroll
        for (int q = 0; q < 4; q++) {
          int off = tid + q * 256;                 // = jj*8 + b, jj in [0,128)
          float r  = sigm(s_sum[off]);
          float z  = sigm(s_sum[H * BC + off]);
          float n  = tanh_fast(s_gxn[off] + r * s_ghn[off]);
          float hp = s_h[l * (H * BC) + off];
          float hn = fmaf(z, hp - n, n);           // (1-z)*n + z*h
          s_h[l * (H * BC) + off] = hn;
          s_x[off] = hn;                           // input to next layer / step
        }
      }
      __syncthreads();

      // fc head on the top-layer output (this step's recorded output).
      if (l == 2 && tid < 256) {
        int s = tid & 15;
        int o = (tid >> 4) & 1;
        int b = tid >> 5;
        float p = 0.0f;
#pragma unroll
        for (int m = 0; m < 8; m++) {
          int k = s * 8 + m;
          p = fmaf(s_fcw[o * H + k], s_x[k * 8 + b], p);
        }
        p += __shfl_down_sync(0xffffffffu, p, 8, 16);
        p += __shfl_down_sync(0xffffffffu, p, 4, 16);
        p += __shfl_down_sync(0xffffffffu, p, 2, 16);
        p += __shfl_down_sync(0xffffffffu, p, 1, 16);
        if (s == 0) out[((b0 + b) * T + t) * 2 + o] = p + s_fcb[o];
      }
      // No barrier needed: next gemv only reads s_x; next combine's writes to
      // s_x are fenced by the next gemv's post-write __syncthreads().
    }
  }
}

extern "C" void kernel_launch(void* const* d_in, const int* in_sizes, int n_in,
                              void* d_out, int out_size) {
  (void)in_sizes; (void)n_in; (void)out_size;
  const float* hiddens = (const float*)d_in[0];
  const float* W_ih    = (const float*)d_in[1];
  const float* W_hh    = (const float*)d_in[2];
  const float* b_ih    = (const float*)d_in[3];
  const float* b_hh    = (const float*)d_in[4];
  const float* fc_w    = (const float*)d_in[5];
  const float* fc_b    = (const float*)d_in[6];
  float* out = (float*)d_out;

  const int prep_elems = LAYERS * KK * G3;
  prep_kernel<<<(prep_elems + 255) / 256, 256>>>(W_ih, W_hh);
  gru_kernel<<<NBLK, NTHR>>>(hiddens, b_ih, b_hh, fc_w, fc_b, out);
}

// round 4
// speedup vs baseline: 1.5534x; 1.5534x over previous
#include <cuda_runtime.h>

// ----------------------------------------------------------------------------
// RNNDecoder: 3-layer GRU (H=128), T=256, B=1024, fc head (out=2).
//
// R3 design: 128 CTAs x 128 threads. Thread `tid` owns gate rows
// {tid (r), tid+128 (z), tid+256 (n)} of both GEMVs for BC=8 batch rows.
//   - L1-wavefront diet: 4 warps instead of 12 reading the broadcast
//     activation stream (2048 LDS-wf/cell vs 6144) -> FMA-bound.
//   - Gate combine fully in registers (thread holds r,z,n of its hidden unit).
//   - fma.rn.f32x2 packed pairs of batch rows; weights pre-transposed so a
//     warp's weight LDG.128 covers 512B contiguous.
//   - Software pipelining: weights prefetched one kk ahead, activations one
//     k ahead (1 warp/SMSP has no other warp to hide latency).
// ----------------------------------------------------------------------------

namespace {
constexpr int LAYERS = 3;
constexpr int H      = 128;
constexpr int G3     = 3 * H;
constexpr int T      = 256;
constexpr int BC     = 8;
constexpr int NTHR   = 128;
constexpr int NBLK   = 128;          // 1024 / BC
constexpr int KK     = H / 4;        // 32 float4 chunks along K
}

// Transposed weights: [l][kk][arr(ih=0,hh=1)][g(r,z,n)][tid] float4.
__device__ float4 g_wt[LAYERS * KK * 2 * 3 * 128];

__global__ void prep_kernel(const float* __restrict__ wih,
                            const float* __restrict__ whh) {
  int idx = blockIdx.x * blockDim.x + threadIdx.x;
  if (idx >= LAYERS * KK * 2 * 3 * 128) return;
  int t   = idx % 128;
  int g   = (idx / 128) % 3;
  int arr = (idx / (128 * 3)) % 2;
  int kk  = (idx / (128 * 3 * 2)) % KK;
  int l   = idx / (128 * 3 * 2 * KK);
  const float* src = (arr ? whh : wih) + (l * G3 + g * 128 + t) * H + kk * 4;
  g_wt[idx] = *reinterpret_cast<const float4*>(src);
}

__device__ __forceinline__ void ffma2(unsigned long long& a,
                                      unsigned long long w,
                                      unsigned long long x) {
  asm("fma.rn.f32x2 %0, %1, %2, %0;" : "+l"(a) : "l"(w), "l"(x));
}
__device__ __forceinline__ unsigned long long dup2(float w) {
  unsigned long long r;
  asm("mov.b64 %0, {%1, %1};" : "=l"(r) : "f"(w));
  return r;
}
__device__ __forceinline__ float2 unpk(unsigned long long v) {
  float lo, hi;
  asm("mov.b64 {%0, %1}, %2;" : "=f"(lo), "=f"(hi) : "l"(v));
  return make_float2(lo, hi);
}
__device__ __forceinline__ float sigm(float x) {
  return __fdividef(1.0f, 1.0f + __expf(-x));
}
__device__ __forceinline__ float tanh_fast(float v) {
  float a = fabsf(v);
  float e = __expf(-2.0f * a);
  float r = __fdividef(1.0f - e, 1.0f + e);
  return copysignf(r, v);
}
__device__ __forceinline__ float comp(const float4& v, int e) {
  return e == 0 ? v.x : e == 1 ? v.y : e == 2 ? v.z : v.w;
}

__global__ void __launch_bounds__(NTHR, 1)
gru_kernel(const float* __restrict__ hiddens,
           const float* __restrict__ b_ih,
           const float* __restrict__ b_hh,
           const float* __restrict__ fc_w,
           const float* __restrict__ fc_b,
           float* __restrict__ out) {
  __shared__ __align__(16) float s_x[H * BC];            // [k][b]
  __shared__ __align__(16) float s_h[LAYERS * H * BC];   // [l][k][b]
  __shared__ float s_fcw[2 * H];
  __shared__ float s_fcb[2];

  const int tid = threadIdx.x;
  const int b0  = blockIdx.x * BC;

  // Biases for this thread's hidden unit (r,z summed; n kept split).
  float brz_r[LAYERS], brz_z[LAYERS], bn_x[LAYERS], bn_h[LAYERS];
#pragma unroll
  for (int l = 0; l < LAYERS; l++) {
    brz_r[l] = b_ih[l * G3 + tid]       + b_hh[l * G3 + tid];
    brz_z[l] = b_ih[l * G3 + 128 + tid] + b_hh[l * G3 + 128 + tid];
    bn_x[l]  = b_ih[l * G3 + 256 + tid];
    bn_h[l]  = b_hh[l * G3 + 256 + tid];
  }
  s_fcw[tid]       = fc_w[tid];
  s_fcw[tid + 128] = fc_w[tid + 128];
  if (tid < 2) s_fcb[tid] = fc_b[tid];

  // h init: hiddens[b][l][k] -> s_h[l][k][b]
  for (int i = tid; i < LAYERS * H * BC; i += NTHR) {
    int l = i >> 10, rem = i & 1023, k = rem >> 3, b = rem & 7;
    s_h[i] = hiddens[(b0 + b) * (LAYERS * H) + l * H + k];
  }
  for (int i = tid; i < H * BC; i += NTHR) s_x[i] = 0.0f;
  __syncthreads();

  for (int t = 0; t < T; t++) {
#pragma unroll 1
    for (int l = 0; l < LAYERS; l++) {
      const float* __restrict__  hl = s_h + l * (H * BC);
      const float4* __restrict__ wp = g_wt + l * (KK * 6 * 128) + tid;

      unsigned long long acc[3][2][4];
#pragma unroll
      for (int g = 0; g < 3; g++)
#pragma unroll
        for (int a = 0; a < 2; a++)
#pragma unroll
          for (int q = 0; q < 4; q++) acc[g][a][q] = 0ull;

      // Prefetch kk=0 weights and k=0 activations.
      float4 wv[2][3], wn[2][3];
#pragma unroll
      for (int a = 0; a < 2; a++)
#pragma unroll
        for (int g = 0; g < 3; g++)
          wn[a][g] = wp[(a * 3 + g) * 128];
      ulonglong2 xc0 = *reinterpret_cast<const ulonglong2*>(s_x);
      ulonglong2 xc1 = *reinterpret_cast<const ulonglong2*>(s_x + 4);
      ulonglong2 hc0 = *reinterpret_cast<const ulonglong2*>(hl);
      ulonglong2 hc1 = *reinterpret_cast<const ulonglong2*>(hl + 4);

#pragma unroll 2
      for (int kk = 0; kk < KK; kk++) {
        // rotate weights; prefetch next kk (wrap reload at the end, discarded)
#pragma unroll
        for (int a = 0; a < 2; a++)
#pragma unroll
          for (int g = 0; g < 3; g++) {
            wv[a][g] = wn[a][g];
            wn[a][g] = wp[((((kk + 1) & 31) * 6) + a * 3 + g) * 128];
          }
#pragma unroll
        for (int e = 0; e < 4; e++) {
          int kn = ((kk * 4 + e) + 1) & 127;   // prefetch next k's activations
          ulonglong2 xn0 = *reinterpret_cast<const ulonglong2*>(s_x + kn * 8);
          ulonglong2 xn1 = *reinterpret_cast<const ulonglong2*>(s_x + kn * 8 + 4);
          ulonglong2 hn0 = *reinterpret_cast<const ulonglong2*>(hl + kn * 8);
          ulonglong2 hn1 = *reinterpret_cast<const ulonglong2*>(hl + kn * 8 + 4);
#pragma unroll
          for (int g = 0; g < 3; g++) {
            unsigned long long dx = dup2(comp(wv[0][g], e));
            ffma2(acc[g][0][0], dx, xc0.x);
            ffma2(acc[g][0][1], dx, xc0.y);
            ffma2(acc[g][0][2], dx, xc1.x);
            ffma2(acc[g][0][3], dx, xc1.y);
            unsigned long long dh = dup2(comp(wv[1][g], e));
            ffma2(acc[g][1][0], dh, hc0.x);
            ffma2(acc[g][1][1], dh, hc0.y);
            ffma2(acc[g][1][2], dh, hc1.x);
            ffma2(acc[g][1][3], dh, hc1.y);
          }
          xc0 = xn0; xc1 = xn1; hc0 = hn0; hc1 = hn1;
        }
      }

      __syncthreads();  // all gemv smem reads done before state rewrite

      // Register-resident gate combine for hidden unit `tid`, 8 batch rows.
      float4 hp0 = *reinterpret_cast<const float4*>(hl + tid * 8);
      float4 hp1 = *reinterpret_cast<const float4*>(hl + tid * 8 + 4);
      float hp[8] = {hp0.x, hp0.y, hp0.z, hp0.w, hp1.x, hp1.y, hp1.z, hp1.w};
      float hv[8];
#pragma unroll
      for (int q = 0; q < 4; q++) {
        float2 xr = unpk(acc[0][0][q]), hr = unpk(acc[0][1][q]);
        float2 xz = unpk(acc[1][0][q]), hz = unpk(acc[1][1][q]);
        float2 xn = unpk(acc[2][0][q]), hn = unpk(acc[2][1][q]);
        {
          float r = sigm(xr.x + hr.x + brz_r[l]);
          float z = sigm(xz.x + hz.x + brz_z[l]);
          float n = tanh_fast(xn.x + bn_x[l] + r * (hn.x + bn_h[l]));
          hv[q * 2 + 0] = fmaf(z, hp[q * 2 + 0] - n, n);
        }
        {
          float r = sigm(xr.y + hr.y + brz_r[l]);
          float z = sigm(xz.y + hz.y + brz_z[l]);
          float n = tanh_fast(xn.y + bn_x[l] + r * (hn.y + bn_h[l]));
          hv[q * 2 + 1] = fmaf(z, hp[q * 2 + 1] - n, n);
        }
      }
      float4 o0 = make_float4(hv[0], hv[1], hv[2], hv[3]);
      float4 o1 = make_float4(hv[4], hv[5], hv[6], hv[7]);
      *reinterpret_cast<float4*>(s_h + l * (H * BC) + tid * 8)     = o0;
      *reinterpret_cast<float4*>(s_h + l * (H * BC) + tid * 8 + 4) = o1;
      *reinterpret_cast<float4*>(s_x + tid * 8)                    = o0;
      *reinterpret_cast<float4*>(s_x + tid * 8 + 4)                = o1;
      __syncthreads();

      // fc head on top-layer output; 16 outputs spread over 4 warps,
      // 8 lanes per output, 16 k each, shfl-reduced within 8-lane groups.
      if (l == 2) {
        int wid = tid >> 5, lid = tid & 31;
        int oid = wid * 4 + (lid >> 3);     // 0..15
        int o = oid & 1, b = oid >> 1;
        int kb = (lid & 7) * 16;
        float p = 0.0f;
#pragma unroll
        for (int m = 0; m < 16; m++)
          p = fmaf(s_fcw[o * H + kb + m], s_x[(kb + m) * 8 + b], p);
        p += __shfl_down_sync(0xffffffffu, p, 4, 8);
        p += __shfl_down_sync(0xffffffffu, p, 2, 8);
        p += __shfl_down_sync(0xffffffffu, p, 1, 8);
        if ((lid & 7) == 0) out[((b0 + b) * T + t) * 2 + o] = p + s_fcb[o];
      }
    }
  }
}

extern "C" void kernel_launch(void* const* d_in, const int* in_sizes, int n_in,
                              void* d_out, int out_size) {
  (void)in_sizes; (void)n_in; (void)out_size;
  const float* hiddens = (const float*)d_in[0];
  const float* W_ih    = (const float*)d_in[1];
  const float* W_hh    = (const float*)d_in[2];
  const float* b_ih    = (const float*)d_in[3];
  const float* b_hh    = (const float*)d_in[4];
  const float* fc_w    = (const float*)d_in[5];
  const float* fc_b    = (const float*)d_in[6];
  float* out = (float*)d_out;

  const int prep_elems = LAYERS * KK * 2 * 3 * 128;
  prep_kernel<<<(prep_elems + 255) / 256, 256>>>(W_ih, W_hh);
  gru_kernel<<<NBLK, NTHR>>>(hiddens, b_ih, b_hh, fc_w, fc_b, out);
}